// round 3
// baseline (speedup 1.0000x reference)
#include <cuda_runtime.h>
#include <math_constants.h>
#include <cstdint>

// CrossEntropy: B=16384 rows, C=4096 cols.
// loss[b] = log(sum_c exp(p[b,c])) - sum_{c: t==1} p[b,c],  p = softmax(x, axis=1)
// output  = mean_b loss[b]   (single fp32 scalar)
//
// R3 (= R2 + compile fix): 4 rows/CTA with per-block loss partials, cp.async
// double-buffered prefetch of the target stream into smem, __ldcs streaming
// loads for the logits.

#define B_ROWS 16384
#define C_COLS 4096
#define TPB    256
#define NWARPS (TPB / 32)
#define VPT    4                    // float4/int4 chunks per thread (16 elems)
#define ROWS_PER_CTA 4
#define NBLK   (B_ROWS / ROWS_PER_CTA)   // 4096

__device__ float g_part[NBLK];      // per-block loss partial sums

__device__ __forceinline__ float warp_reduce_sum(float v) {
#pragma unroll
    for (int o = 16; o > 0; o >>= 1) v += __shfl_xor_sync(0xFFFFFFFFu, v, o);
    return v;
}
__device__ __forceinline__ float warp_reduce_max(float v) {
#pragma unroll
    for (int o = 16; o > 0; o >>= 1) v = fmaxf(v, __shfl_xor_sync(0xFFFFFFFFu, v, o));
    return v;
}

__device__ __forceinline__ float block_reduce_sum(float v, float* sh, int tid) {
    v = warp_reduce_sum(v);
    if ((tid & 31) == 0) sh[tid >> 5] = v;
    __syncthreads();
    float r = 0.0f;
#pragma unroll
    for (int i = 0; i < NWARPS; i++) r += sh[i];
    __syncthreads();
    return r;
}
__device__ __forceinline__ float block_reduce_max(float v, float* sh, int tid) {
    v = warp_reduce_max(v);
    if ((tid & 31) == 0) sh[tid >> 5] = v;
    __syncthreads();
    float r = -CUDART_INF_F;
#pragma unroll
    for (int i = 0; i < NWARPS; i++) r = fmaxf(r, sh[i]);
    __syncthreads();
    return r;
}

// cp.async 16B global->shared (L2 path, bypass L1)
__device__ __forceinline__ void cp_async16(void* smem_dst, const void* gmem_src) {
    unsigned int s = (unsigned int)__cvta_generic_to_shared(smem_dst);
    asm volatile("cp.async.cg.shared.global [%0], [%1], 16;\n" :: "r"(s), "l"(gmem_src));
}
__device__ __forceinline__ void cp_async_commit() {
    asm volatile("cp.async.commit_group;\n" ::: "memory");
}
template <int N>
__device__ __forceinline__ void cp_async_wait() {
    asm volatile("cp.async.wait_group %0;\n" :: "n"(N) : "memory");
}

__global__ __launch_bounds__(TPB)
void ce_row_kernel(const float* __restrict__ x, const int* __restrict__ t) {
    const int tid = threadIdx.x;
    const int row0 = blockIdx.x * ROWS_PER_CTA;

    __shared__ int4  sh_t[2][C_COLS / 4];   // 2 x 16KB target double buffer
    __shared__ float sh_red[NWARPS];

    // Prologue: prefetch target row 0 into buffer 0.
    {
        const int4* tg = reinterpret_cast<const int4*>(t + (size_t)row0 * C_COLS);
#pragma unroll
        for (int i = 0; i < VPT; i++)
            cp_async16(&sh_t[0][tid + i * TPB], tg + tid + i * TPB);
        cp_async_commit();
    }

    float loss_acc = 0.0f;   // meaningful on tid 0 only

#pragma unroll
    for (int r = 0; r < ROWS_PER_CTA; r++) {
        const int row = row0 + r;
        const int buf = r & 1;

        // Prefetch next row's target into the other buffer.
        if (r + 1 < ROWS_PER_CTA) {
            const int4* tg = reinterpret_cast<const int4*>(t + (size_t)(row + 1) * C_COLS);
#pragma unroll
            for (int i = 0; i < VPT; i++)
                cp_async16(&sh_t[buf ^ 1][tid + i * TPB], tg + tid + i * TPB);
            cp_async_commit();
        }

        // ---- Phase 1: stream logits into registers, row max ----
        const float4* x4 = reinterpret_cast<const float4*>(x + (size_t)row * C_COLS);
        float4 v[VPT];
        float lmax = -CUDART_INF_F;
#pragma unroll
        for (int i = 0; i < VPT; i++) {
            v[i] = __ldcs(x4 + tid + i * TPB);
            lmax = fmaxf(lmax, fmaxf(fmaxf(v[i].x, v[i].y), fmaxf(v[i].z, v[i].w)));
        }
        const float m = block_reduce_max(lmax, sh_red, tid);

        // ---- Phase 2: exp(x - m), softmax denominator ----
        float lsum = 0.0f;
#pragma unroll
        for (int i = 0; i < VPT; i++) {
            v[i].x = __expf(v[i].x - m);
            v[i].y = __expf(v[i].y - m);
            v[i].z = __expf(v[i].z - m);
            v[i].w = __expf(v[i].w - m);
            lsum += (v[i].x + v[i].y) + (v[i].z + v[i].w);
        }
        // Ensure this row's target copies have landed; the barrier inside the
        // following block reduce publishes them block-wide.
        if (r + 1 < ROWS_PER_CTA) cp_async_wait<1>(); else cp_async_wait<0>();
        const float denom = block_reduce_sum(lsum, sh_red, tid);
        const float rinv  = __fdividef(1.0f, denom);

        // ---- Phase 3: p = e * rinv; sum exp(p) and p*mask (t from smem) ----
        float a = 0.0f, b = 0.0f;
#pragma unroll
        for (int i = 0; i < VPT; i++) {
            int4 ti = sh_t[buf][tid + i * TPB];
            float px = v[i].x * rinv;
            float py = v[i].y * rinv;
            float pz = v[i].z * rinv;
            float pw = v[i].w * rinv;
            a += (__expf(px) + __expf(py)) + (__expf(pz) + __expf(pw));
            if (ti.x == 1) b += px;
            if (ti.y == 1) b += py;
            if (ti.z == 1) b += pz;
            if (ti.w == 1) b += pw;
        }
        const float A = block_reduce_sum(a, sh_red, tid);
        const float M = block_reduce_sum(b, sh_red, tid);
        // trailing __syncthreads inside the reduce guards sh_t reuse next iter

        if (tid == 0) loss_acc += __logf(A) - M;
    }

    if (tid == 0) g_part[blockIdx.x] = loss_acc;
}

// Deterministic fixed-order mean over 4096 per-block partials (16 KB).
__global__ __launch_bounds__(1024)
void ce_mean_kernel(float* __restrict__ out) {
    __shared__ float sh[32];
    const int tid = threadIdx.x;
    float s = 0.0f;
#pragma unroll
    for (int i = 0; i < NBLK / 1024; i++) s += g_part[tid + i * 1024];
    s = warp_reduce_sum(s);
    if ((tid & 31) == 0) sh[tid >> 5] = s;
    __syncthreads();
    if (tid < 32) {
        float r = sh[tid];
        r = warp_reduce_sum(r);
        if (tid == 0) out[0] = r * (1.0f / (float)B_ROWS);
    }
}

extern "C" void kernel_launch(void* const* d_in, const int* in_sizes, int n_in,
                              void* d_out, int out_size) {
    const float* x = (const float*)d_in[0];   // logits fp32 [B, C]
    const int*   t = (const int*)d_in[1];     // multi-hot int32 [B, C]
    float* out = (float*)d_out;               // scalar fp32

    ce_row_kernel<<<NBLK, TPB>>>(x, t);
    ce_mean_kernel<<<1, 1024>>>(out);
}